// round 7
// baseline (speedup 1.0000x reference)
#include <cuda_runtime.h>

#define B_   64
#define LX_  512
#define LY_  512
#define DIM_ 64
#define BIGF 1e30f

// Diagonal-major scratch: g_Dt[b][t][i] = D[b][i][t - i], t in [0, 1023)
__device__ float g_Dt[(size_t)B_ * 1024 * 512];

typedef unsigned long long u64;

__device__ __forceinline__ u64 pack2(float lo, float hi) {
    u64 r; asm("mov.b64 %0,{%1,%2};" : "=l"(r) : "f"(lo), "f"(hi)); return r;
}
__device__ __forceinline__ u64 ffma2(u64 a, u64 b, u64 c) {
    u64 d; asm("fma.rn.f32x2 %0,%1,%2,%3;" : "=l"(d) : "l"(a), "l"(b), "l"(c)); return d;
}
__device__ __forceinline__ float2 unpack2(u64 v) {
    float2 f; asm("mov.b64 {%0,%1},%2;" : "=f"(f.x), "=f"(f.y) : "l"(v)); return f;
}
__device__ __forceinline__ float ex2_approx(float x) {
    float r; asm("ex2.approx.ftz.f32 %0,%1;" : "=f"(r) : "f"(x)); return r;
}
__device__ __forceinline__ float lg2_approx(float x) {
    float r; asm("lg2.approx.ftz.f32 %0,%1;" : "=f"(r) : "f"(x)); return r;
}

#define TP 132

// ---------------------------------------------------------------------------
// Kernel 1: batched pairwise squared-L2, 128x128 tiles, 256 threads,
// 8x8 micro-tiles, diagonal-major writeout (unchanged).
// ---------------------------------------------------------------------------
__global__ __launch_bounds__(256) void sdtw_gemm_kernel(
    const float* __restrict__ X, const float* __restrict__ Y)
{
    __shared__ float pool[2 * 32 * TP];
    float* Xs = pool;
    float* Ys = pool + 32 * TP;

    const int b  = blockIdx.z;
    const int i0 = blockIdx.y * 128;
    const int j0 = blockIdx.x * 128;
    const int tid = threadIdx.x;
    const int tx = tid & 15;
    const int ty = tid >> 4;

    const float* Xb = X + ((size_t)b * LX_ + i0) * DIM_;
    const float* Yb = Y + ((size_t)b * LY_ + j0) * DIM_;

    u64 acc2[8][4];
    u64 xn2[4], yn2[4];
    const u64 z = pack2(0.f, 0.f);
#pragma unroll
    for (int r = 0; r < 8; ++r)
#pragma unroll
        for (int p = 0; p < 4; ++p) acc2[r][p] = z;
#pragma unroll
    for (int p = 0; p < 4; ++p) { xn2[p] = z; yn2[p] = z; }

#pragma unroll 1
    for (int kh = 0; kh < 2; ++kh) {
        __syncthreads();
#pragma unroll
        for (int it = 0; it < 4; ++it) {
            int f4  = it * 256 + tid;
            int row = f4 >> 3;
            int k4  = (f4 & 7) << 2;
            float4 xv = *(const float4*)(Xb + row * DIM_ + kh * 32 + k4);
            Xs[(k4 + 0) * TP + row] = xv.x; Xs[(k4 + 1) * TP + row] = xv.y;
            Xs[(k4 + 2) * TP + row] = xv.z; Xs[(k4 + 3) * TP + row] = xv.w;
            float4 yv = *(const float4*)(Yb + row * DIM_ + kh * 32 + k4);
            Ys[(k4 + 0) * TP + row] = yv.x; Ys[(k4 + 1) * TP + row] = yv.y;
            Ys[(k4 + 2) * TP + row] = yv.z; Ys[(k4 + 3) * TP + row] = yv.w;
        }
        __syncthreads();

#pragma unroll 8
        for (int k = 0; k < 32; ++k) {
            float4 xa = *(const float4*)&Xs[k * TP + ty * 8];
            float4 xb = *(const float4*)&Xs[k * TP + ty * 8 + 4];
            float4 ya = *(const float4*)&Ys[k * TP + tx * 8];
            float4 yb = *(const float4*)&Ys[k * TP + tx * 8 + 4];
            u64 yp[4] = { pack2(ya.x, ya.y), pack2(ya.z, ya.w),
                          pack2(yb.x, yb.y), pack2(yb.z, yb.w) };
            float xs[8] = {xa.x, xa.y, xa.z, xa.w, xb.x, xb.y, xb.z, xb.w};
#pragma unroll
            for (int r = 0; r < 8; ++r) {
                u64 xp = pack2(xs[r], xs[r]);
#pragma unroll
                for (int p = 0; p < 4; ++p)
                    acc2[r][p] = ffma2(xp, yp[p], acc2[r][p]);
            }
            u64 xq[4] = { pack2(xa.x, xa.y), pack2(xa.z, xa.w),
                          pack2(xb.x, xb.y), pack2(xb.z, xb.w) };
#pragma unroll
            for (int p = 0; p < 4; ++p) {
                xn2[p] = ffma2(xq[p], xq[p], xn2[p]);
                yn2[p] = ffma2(yp[p], yp[p], yn2[p]);
            }
        }
    }

    float xn[8], yn[8], dres[8][8];
#pragma unroll
    for (int p = 0; p < 4; ++p) {
        float2 xv = unpack2(xn2[p]); xn[2*p] = xv.x; xn[2*p+1] = xv.y;
        float2 yv = unpack2(yn2[p]); yn[2*p] = yv.x; yn[2*p+1] = yv.y;
    }
#pragma unroll
    for (int r = 0; r < 8; ++r)
#pragma unroll
        for (int p = 0; p < 4; ++p) {
            float2 a = unpack2(acc2[r][p]);
            dres[r][2*p]   = fmaf(-2.0f, a.x, xn[r] + yn[2*p]);
            dres[r][2*p+1] = fmaf(-2.0f, a.y, xn[r] + yn[2*p+1]);
        }

    const int CP = 66;
    float* stage = pool;
    const int g  = tid >> 6;
    const int li = tid & 63;
#pragma unroll 1
    for (int q = 0; q < 4; ++q) {
        int qi = q >> 1, qj = q & 1;
        __syncthreads();
        if ((ty >> 3) == qi && (tx >> 3) == qj) {
            int r0 = (ty & 7) * 8, c0 = (tx & 7) * 8;
#pragma unroll
            for (int r = 0; r < 8; ++r)
#pragma unroll
                for (int c = 0; c < 8; ++c)
                    stage[(r0 + r) * CP + (c0 + c)] = dres[r][c];
        }
        __syncthreads();
        int i0q = i0 + qi * 64, j0q = j0 + qj * 64;
        float* Dtb = g_Dt + (size_t)b * (1024 * 512)
                   + (size_t)(i0q + j0q) * 512 + i0q;
        for (int tl = g; tl < 127; tl += 4) {
            int ilo = tl - 63; if (ilo < 0) ilo = 0;
            int ihi = tl;      if (ihi > 63) ihi = 63;
            if (li >= ilo && li <= ihi)
                Dtb[(size_t)tl * 512 + li] = stage[li * (CP - 1) + tl];
        }
    }
}

// ---------------------------------------------------------------------------
// Kernel 2: warp-pipelined soft-DTW wavefront.
// One shfl/step (diag dep = previous step's up, in prev_up); lane-0 boundary
// via warp-uniform LDS broadcast + SEL; single-instruction MUFU (ex2/lg2
// approx via asm); bottom-row publish = ONE predicated STS from lane 31.
// Spurious padded step s=543 is harmless (all lanes j>511); answer is read
// from bnd[15][512], written exactly once at s=542.
// ---------------------------------------------------------------------------
__global__ __launch_bounds__(512) void sdtw_dp_kernel(float* __restrict__ out)
{
    __shared__ float bnd[16][520];   // bnd[w][c+1] = R[32w+31][c]; [w][0]=BIG

    const int tid = threadIdx.x;
    const int w = tid >> 5;
    const int l = tid & 31;
    const int b = blockIdx.x;

    if (l == 0) bnd[w][0] = BIGF;

    // DW[s*512] = Dt[b][32w+s][32w+l]
    const float* __restrict__ DW =
        g_Dt + (size_t)b * (1024 * 512) + (size_t)(32 * w) * 512 + 32 * w + l;

    float a1 = BIGF;                             // R[i][j-1]
    float prev_up = (tid == 0) ? 0.0f : BIGF;    // becomes diag dep next step
    float dring[8];
#pragma unroll
    for (int u = 0; u < 8; ++u) dring[u] = __ldg(DW + (size_t)u * 512);

    __syncthreads();

    const float L2E = 1.44269504f;
    const float LN2 = 0.69314718f;
    const int NCH = 34;              // ceil(543/16); last chunk pads to s=543
    const int LAG = 3;
    const int P = 15 * LAG + NCH;    // 79 phases
    const float* bprev = bnd[(w > 0) ? (w - 1) : 0];
    const bool lane0   = (l == 0);
    const bool w0lane0 = (w == 0) && lane0;
    const bool lane31  = (l == 31);

#pragma unroll 1
    for (int p = 0; p < P; ++p) {
        int q = p - LAG * w;
        if (q >= 0 && q < NCH) {                 // warp-uniform
            int s0 = q * 16;
#pragma unroll
            for (int u = 0; u < 16; ++u) {
                int s = s0 + u;
                float d = dring[u & 7];
                int sp = s + 8; if (sp > 542) sp = 542;
                dring[u & 7] = __ldg(DW + (size_t)sp * 512);

                // warp-uniform boundary load (address depends only on s)
                int jc0 = (s > 511) ? 511 : s;
                float bup = bprev[jc0 + 1];      // R[32w-1][s] (broadcast)

                float up_sh = __shfl_up_sync(0xFFFFFFFFu, a1, 1);
                float up = lane0 ? (w0lane0 ? BIGF : bup) : up_sh;
                float dg = prev_up;              // == up from previous step
                int j = s - l;
                float lf = (j >= 1) ? a1 : BIGF;

                // softmin via sort3 (exp of the min folded to 1)
                float mn = fminf(up, dg), mx = fmaxf(up, dg);
                float m  = fminf(mn, lf);
                float md = fmaxf(mn, fminf(mx, lf));
                float hi = fmaxf(mx, lf);
                float mc = m * L2E;
                float e1 = ex2_approx(fmaf(-L2E, md, mc));
                float e2 = ex2_approx(fmaf(-L2E, hi, mc));
                float smin = fmaf(-LN2, lg2_approx(1.0f + e1 + e2), m);

                float rc = ((unsigned)j <= 511u) ? (d + smin) : BIGF;
                prev_up = up;
                a1 = rc;

                // single predicated STS publish of bottom row
                if (lane31 && (unsigned)j <= 511u) bnd[w][j + 1] = rc;
            }
        }
        __syncthreads();
    }

    // R[511][511] published by warp 15, lane 31 at s=542 (j=511).
    if (tid == 0) out[b] = bnd[15][512];
}

// ---------------------------------------------------------------------------
extern "C" void kernel_launch(void* const* d_in, const int* in_sizes, int n_in,
                              void* d_out, int out_size)
{
    (void)in_sizes; (void)n_in; (void)out_size;
    const float* X = (const float*)d_in[0];
    const float* Y = (const float*)d_in[1];
    float* out = (float*)d_out;

    dim3 gg(LY_ / 128, LX_ / 128, B_);
    sdtw_gemm_kernel<<<gg, 256>>>(X, Y);
    sdtw_dp_kernel<<<B_, 512>>>(out);
}

// round 8
// speedup vs baseline: 1.5817x; 1.5817x over previous
#include <cuda_runtime.h>

#define B_   64
#define LX_  512
#define LY_  512
#define DIM_ 64
#define BIGF 1e30f

// Diagonal-major scratch: g_Dt[b][t][i] = D[b][i][t - i], t in [0, 1023)
__device__ float g_Dt[(size_t)B_ * 1024 * 512];

typedef unsigned long long u64;

__device__ __forceinline__ u64 pack2(float lo, float hi) {
    u64 r; asm("mov.b64 %0,{%1,%2};" : "=l"(r) : "f"(lo), "f"(hi)); return r;
}
__device__ __forceinline__ u64 ffma2(u64 a, u64 b, u64 c) {
    u64 d; asm("fma.rn.f32x2 %0,%1,%2,%3;" : "=l"(d) : "l"(a), "l"(b), "l"(c)); return d;
}
__device__ __forceinline__ float2 unpack2(u64 v) {
    float2 f; asm("mov.b64 {%0,%1},%2;" : "=f"(f.x), "=f"(f.y) : "l"(v)); return f;
}
__device__ __forceinline__ float ex2_approx(float x) {
    float r; asm("ex2.approx.ftz.f32 %0,%1;" : "=f"(r) : "f"(x)); return r;
}
__device__ __forceinline__ float lg2_approx(float x) {
    float r; asm("lg2.approx.ftz.f32 %0,%1;" : "=f"(r) : "f"(x)); return r;
}

#define TP 132

// ---------------------------------------------------------------------------
// Kernel 1: batched pairwise squared-L2, 128x128 tiles, 256 threads,
// 8x8 micro-tiles, diagonal-major writeout (unchanged).
// ---------------------------------------------------------------------------
__global__ __launch_bounds__(256) void sdtw_gemm_kernel(
    const float* __restrict__ X, const float* __restrict__ Y)
{
    __shared__ float pool[2 * 32 * TP];
    float* Xs = pool;
    float* Ys = pool + 32 * TP;

    const int b  = blockIdx.z;
    const int i0 = blockIdx.y * 128;
    const int j0 = blockIdx.x * 128;
    const int tid = threadIdx.x;
    const int tx = tid & 15;
    const int ty = tid >> 4;

    const float* Xb = X + ((size_t)b * LX_ + i0) * DIM_;
    const float* Yb = Y + ((size_t)b * LY_ + j0) * DIM_;

    u64 acc2[8][4];
    u64 xn2[4], yn2[4];
    const u64 z = pack2(0.f, 0.f);
#pragma unroll
    for (int r = 0; r < 8; ++r)
#pragma unroll
        for (int p = 0; p < 4; ++p) acc2[r][p] = z;
#pragma unroll
    for (int p = 0; p < 4; ++p) { xn2[p] = z; yn2[p] = z; }

#pragma unroll 1
    for (int kh = 0; kh < 2; ++kh) {
        __syncthreads();
#pragma unroll
        for (int it = 0; it < 4; ++it) {
            int f4  = it * 256 + tid;
            int row = f4 >> 3;
            int k4  = (f4 & 7) << 2;
            float4 xv = *(const float4*)(Xb + row * DIM_ + kh * 32 + k4);
            Xs[(k4 + 0) * TP + row] = xv.x; Xs[(k4 + 1) * TP + row] = xv.y;
            Xs[(k4 + 2) * TP + row] = xv.z; Xs[(k4 + 3) * TP + row] = xv.w;
            float4 yv = *(const float4*)(Yb + row * DIM_ + kh * 32 + k4);
            Ys[(k4 + 0) * TP + row] = yv.x; Ys[(k4 + 1) * TP + row] = yv.y;
            Ys[(k4 + 2) * TP + row] = yv.z; Ys[(k4 + 3) * TP + row] = yv.w;
        }
        __syncthreads();

#pragma unroll 8
        for (int k = 0; k < 32; ++k) {
            float4 xa = *(const float4*)&Xs[k * TP + ty * 8];
            float4 xb = *(const float4*)&Xs[k * TP + ty * 8 + 4];
            float4 ya = *(const float4*)&Ys[k * TP + tx * 8];
            float4 yb = *(const float4*)&Ys[k * TP + tx * 8 + 4];
            u64 yp[4] = { pack2(ya.x, ya.y), pack2(ya.z, ya.w),
                          pack2(yb.x, yb.y), pack2(yb.z, yb.w) };
            float xs[8] = {xa.x, xa.y, xa.z, xa.w, xb.x, xb.y, xb.z, xb.w};
#pragma unroll
            for (int r = 0; r < 8; ++r) {
                u64 xp = pack2(xs[r], xs[r]);
#pragma unroll
                for (int p = 0; p < 4; ++p)
                    acc2[r][p] = ffma2(xp, yp[p], acc2[r][p]);
            }
            u64 xq[4] = { pack2(xa.x, xa.y), pack2(xa.z, xa.w),
                          pack2(xb.x, xb.y), pack2(xb.z, xb.w) };
#pragma unroll
            for (int p = 0; p < 4; ++p) {
                xn2[p] = ffma2(xq[p], xq[p], xn2[p]);
                yn2[p] = ffma2(yp[p], yp[p], yn2[p]);
            }
        }
    }

    float xn[8], yn[8], dres[8][8];
#pragma unroll
    for (int p = 0; p < 4; ++p) {
        float2 xv = unpack2(xn2[p]); xn[2*p] = xv.x; xn[2*p+1] = xv.y;
        float2 yv = unpack2(yn2[p]); yn[2*p] = yv.x; yn[2*p+1] = yv.y;
    }
#pragma unroll
    for (int r = 0; r < 8; ++r)
#pragma unroll
        for (int p = 0; p < 4; ++p) {
            float2 a = unpack2(acc2[r][p]);
            dres[r][2*p]   = fmaf(-2.0f, a.x, xn[r] + yn[2*p]);
            dres[r][2*p+1] = fmaf(-2.0f, a.y, xn[r] + yn[2*p+1]);
        }

    const int CP = 66;
    float* stage = pool;
    const int g  = tid >> 6;
    const int li = tid & 63;
#pragma unroll 1
    for (int q = 0; q < 4; ++q) {
        int qi = q >> 1, qj = q & 1;
        __syncthreads();
        if ((ty >> 3) == qi && (tx >> 3) == qj) {
            int r0 = (ty & 7) * 8, c0 = (tx & 7) * 8;
#pragma unroll
            for (int r = 0; r < 8; ++r)
#pragma unroll
                for (int c = 0; c < 8; ++c)
                    stage[(r0 + r) * CP + (c0 + c)] = dres[r][c];
        }
        __syncthreads();
        int i0q = i0 + qi * 64, j0q = j0 + qj * 64;
        float* Dtb = g_Dt + (size_t)b * (1024 * 512)
                   + (size_t)(i0q + j0q) * 512 + i0q;
        for (int tl = g; tl < 127; tl += 4) {
            int ilo = tl - 63; if (ilo < 0) ilo = 0;
            int ihi = tl;      if (ihi > 63) ihi = 63;
            if (li >= ilo && li <= ihi)
                Dtb[(size_t)tl * 512 + li] = stage[li * (CP - 1) + tl];
        }
    }
}

// ---------------------------------------------------------------------------
// Kernel 2: warp-pipelined soft-DTW wavefront.
// Depth-16 D prefetch ring (full-chunk coverage, MLP=16); boundary LDS
// software-pipelined one step ahead (off the serial chain); one shfl/step;
// single-instruction MUFU; single predicated STS publish from lane 31.
// Answer read from bnd[15][512] (written once at s=542).
// ---------------------------------------------------------------------------
__global__ __launch_bounds__(512) void sdtw_dp_kernel(float* __restrict__ out)
{
    __shared__ float bnd[16][520];   // bnd[w][c+1] = R[32w+31][c]; [w][0]=BIG

    const int tid = threadIdx.x;
    const int w = tid >> 5;
    const int l = tid & 31;
    const int b = blockIdx.x;

    if (l == 0) bnd[w][0] = BIGF;

    // DW[s*512] = Dt[b][32w+s][32w+l]
    const float* __restrict__ DW =
        g_Dt + (size_t)b * (1024 * 512) + (size_t)(32 * w) * 512 + 32 * w + l;

    float a1 = BIGF;                             // R[i][j-1]
    float prev_up = (tid == 0) ? 0.0f : BIGF;    // becomes diag dep next step
    float dring[16];                             // full-chunk prefetch ring
#pragma unroll
    for (int u = 0; u < 16; ++u) dring[u] = __ldg(DW + (size_t)u * 512);

    __syncthreads();

    const float L2E = 1.44269504f;
    const float LN2 = 0.69314718f;
    const int NCH = 34;              // ceil(543/16); last chunk pads to s=543
    const int LAG = 3;
    const int P = 15 * LAG + NCH;    // 79 phases
    const float* bprev = bnd[(w > 0) ? (w - 1) : 0];
    const bool lane0   = (l == 0);
    const bool w0lane0 = (w == 0) && lane0;
    const bool lane31  = (l == 31);

#pragma unroll 1
    for (int p = 0; p < P; ++p) {
        int q = p - LAG * w;
        if (q >= 0 && q < NCH) {                 // warp-uniform
            int s0 = q * 16;
            // boundary for the chunk's first step (warp-uniform address)
            int jc0 = (s0 > 511) ? 511 : s0;
            float bcur = bprev[jc0 + 1];
#pragma unroll
            for (int u = 0; u < 16; ++u) {
                int s = s0 + u;
                float d = dring[u];
                int sp = s + 16; if (sp > 542) sp = 542;
                dring[u] = __ldg(DW + (size_t)sp * 512);

                // prefetch next step's boundary (stay within this chunk:
                // j = s0+16 may not be published by the producer yet)
                int sn = (u < 15) ? (s + 1) : s;
                int jn = (sn > 511) ? 511 : sn;
                float bnext = bprev[jn + 1];

                float up_sh = __shfl_up_sync(0xFFFFFFFFu, a1, 1);
                float up = lane0 ? (w0lane0 ? BIGF : bcur) : up_sh;
                float dg = prev_up;              // == up from previous step
                int j = s - l;
                float lf = (j >= 1) ? a1 : BIGF;

                // softmin via sort3 (exp of the min folded to 1)
                float mn = fminf(up, dg), mx = fmaxf(up, dg);
                float m  = fminf(mn, lf);
                float md = fmaxf(mn, fminf(mx, lf));
                float hi = fmaxf(mx, lf);
                float mc = m * L2E;
                float e1 = ex2_approx(fmaf(-L2E, md, mc));
                float e2 = ex2_approx(fmaf(-L2E, hi, mc));
                float smin = fmaf(-LN2, lg2_approx(1.0f + e1 + e2), m);

                float rc = ((unsigned)j <= 511u) ? (d + smin) : BIGF;
                prev_up = up;
                a1 = rc;
                bcur = bnext;

                // single predicated STS publish of bottom row
                if (lane31 && (unsigned)j <= 511u) bnd[w][j + 1] = rc;
            }
        }
        __syncthreads();
    }

    // R[511][511] published by warp 15, lane 31 at s=542 (j=511).
    if (tid == 0) out[b] = bnd[15][512];
}

// ---------------------------------------------------------------------------
extern "C" void kernel_launch(void* const* d_in, const int* in_sizes, int n_in,
                              void* d_out, int out_size)
{
    (void)in_sizes; (void)n_in; (void)out_size;
    const float* X = (const float*)d_in[0];
    const float* Y = (const float*)d_in[1];
    float* out = (float*)d_out;

    dim3 gg(LY_ / 128, LX_ / 128, B_);
    sdtw_gemm_kernel<<<gg, 256>>>(X, Y);
    sdtw_dp_kernel<<<B_, 512>>>(out);
}